// round 1
// baseline (speedup 1.0000x reference)
#include <cuda_runtime.h>
#include <math_constants.h>

#define Bb   4
#define Ss   2048
#define HID  2048
#define NH   16
#define NKV  4
#define HD   128
#define MM   (Bb*Ss)   // 8192

// Scratch (device globals: allocation-free)
__device__ float g_Q[MM*NH*HD];    // 8192 x 2048
__device__ float g_K[MM*NKV*HD];   // 8192 x 512
__device__ float g_V[MM*NKV*HD];   // 8192 x 512
__device__ float g_O[MM*NH*HD];    // 8192 x 2048

// ---------------------------------------------------------------------------
// Generic fp32 GEMM: C[M,N] = A[M,K] @ W[N,K]^T   (both row-major, K-contig)
// BM=BN=128, BK=16, 256 threads, 8x8 microtile.
// ---------------------------------------------------------------------------
__global__ __launch_bounds__(256) void gemm_nt(const float* __restrict__ A,
                                               const float* __restrict__ W,
                                               float* __restrict__ C,
                                               int M, int N, int K) {
    __shared__ float As[16*132];
    __shared__ float Ws[16*132];
    int tid = threadIdx.x;
    int tx = tid & 15, ty = tid >> 4;
    int n0 = blockIdx.x * 128, m0 = blockIdx.y * 128;
    int lc = tid & 15, lr = tid >> 4;

    float acc[8][8] = {};
    const float* Ap = A + (size_t)(m0 + lr) * K + lc;
    const float* Wp = W + (size_t)(n0 + lr) * K + lc;

    for (int k0 = 0; k0 < K; k0 += 16) {
        #pragma unroll
        for (int p = 0; p < 8; p++) {
            As[lc*132 + lr + 16*p] = Ap[(size_t)(16*p)*K + k0];
            Ws[lc*132 + lr + 16*p] = Wp[(size_t)(16*p)*K + k0];
        }
        __syncthreads();
        #pragma unroll
        for (int k = 0; k < 16; k++) {
            float4 a0 = *(const float4*)&As[k*132 + ty*8];
            float4 a1 = *(const float4*)&As[k*132 + ty*8 + 4];
            float4 b0 = *(const float4*)&Ws[k*132 + tx*8];
            float4 b1 = *(const float4*)&Ws[k*132 + tx*8 + 4];
            float av[8] = {a0.x,a0.y,a0.z,a0.w,a1.x,a1.y,a1.z,a1.w};
            float bv[8] = {b0.x,b0.y,b0.z,b0.w,b1.x,b1.y,b1.z,b1.w};
            #pragma unroll
            for (int i = 0; i < 8; i++)
                #pragma unroll
                for (int j = 0; j < 8; j++)
                    acc[i][j] += av[i]*bv[j];
        }
        __syncthreads();
    }
    #pragma unroll
    for (int i = 0; i < 8; i++) {
        float4 c0 = {acc[i][0],acc[i][1],acc[i][2],acc[i][3]};
        float4 c1 = {acc[i][4],acc[i][5],acc[i][6],acc[i][7]};
        float* Cp = C + (size_t)(m0 + ty*8 + i)*N + n0 + tx*8;
        *(float4*)Cp       = c0;
        *(float4*)(Cp + 4) = c1;
    }
}

// ---------------------------------------------------------------------------
// RoPE (in place). t: [MM][nh*HD]. cos/sin: [Ss][HD], duplicated halves
// (cos[s][d+64] == cos[s][d]).
// ---------------------------------------------------------------------------
__global__ void rope_kernel(float* __restrict__ t,
                            const float* __restrict__ cosp,
                            const float* __restrict__ sinp, int nh) {
    int idx = blockIdx.x * blockDim.x + threadIdx.x;
    int total = MM * nh * 64;
    if (idx >= total) return;
    int d = idx & 63;
    int h = (idx >> 6) % nh;
    int m = idx / (64 * nh);
    int s = m & (Ss - 1);
    float c  = cosp[s*HD + d];
    float sn = sinp[s*HD + d];
    float* p = t + (size_t)m * nh * HD + h * HD;
    float x1 = p[d], x2 = p[d + 64];
    p[d]      = x1*c - x2*sn;
    p[d + 64] = x2*c + x1*sn;
}

// ---------------------------------------------------------------------------
// Flash attention, fp32, full (non-causal) softmax.
// Grid: (Ss/64, NH, Bb). 256 threads. BM=BN=64, D=128.
// ---------------------------------------------------------------------------
#define SMEM_FLASH ((64*129*2 + 64*128 + 64*65) * 4)

__global__ __launch_bounds__(256) void flash_kernel(const float* __restrict__ Qp,
                                                    const float* __restrict__ Kp,
                                                    const float* __restrict__ Vp,
                                                    float* __restrict__ Op) {
    extern __shared__ float sm[];
    float* Qs = sm;                 // [64][129]
    float* Ks = sm + 64*129;        // [64][129]
    float* Vs = Ks + 64*129;        // [64][128]
    float* Ps = Vs + 64*128;        // [64][65]

    int tid  = threadIdx.x;
    int tx   = tid & 15, ty = tid >> 4;
    int lane = tid & 31, wrp = tid >> 5;
    int h = blockIdx.y, b = blockIdx.z;
    int kv = h >> 2;
    int m0 = b*Ss + blockIdx.x*64;
    const float scale = 0.08838834764831845f;  // 1/sqrt(128)

    // Load Q tile (each warp: 8 rows, one float4/lane/row)
    #pragma unroll
    for (int rr = 0; rr < 8; rr++) {
        int r = wrp*8 + rr;
        float4 v = *(const float4*)&Qp[(size_t)(m0 + r)*(NH*HD) + h*HD + lane*4];
        float* q = &Qs[r*129 + lane*4];
        q[0]=v.x; q[1]=v.y; q[2]=v.z; q[3]=v.w;
    }

    float acc[4][8] = {};
    float mi[4] = {-CUDART_INF_F, -CUDART_INF_F, -CUDART_INF_F, -CUDART_INF_F};
    float li[4] = {0.f, 0.f, 0.f, 0.f};

    for (int n0 = 0; n0 < Ss; n0 += 64) {
        // Load K, V tiles
        #pragma unroll
        for (int rr = 0; rr < 8; rr++) {
            int r = wrp*8 + rr;
            size_t gidx = (size_t)(b*Ss + n0 + r)*(NKV*HD) + kv*HD + lane*4;
            float4 kk = *(const float4*)&Kp[gidx];
            float* kd = &Ks[r*129 + lane*4];
            kd[0]=kk.x; kd[1]=kk.y; kd[2]=kk.z; kd[3]=kk.w;
            float4 vv = *(const float4*)&Vp[gidx];
            *(float4*)&Vs[r*128 + lane*4] = vv;
        }
        __syncthreads();

        // S = Q K^T tile (4x4 per thread)
        float s[4][4] = {};
        #pragma unroll 4
        for (int k = 0; k < 128; k++) {
            float a[4], bb[4];
            #pragma unroll
            for (int i = 0; i < 4; i++) a[i]  = Qs[(ty*4+i)*129 + k];
            #pragma unroll
            for (int j = 0; j < 4; j++) bb[j] = Ks[(tx*4+j)*129 + k];
            #pragma unroll
            for (int i = 0; i < 4; i++)
                #pragma unroll
                for (int j = 0; j < 4; j++)
                    s[i][j] += a[i]*bb[j];
        }

        // Online softmax (row groups of 16 lanes; xor-shuffle reduce)
        #pragma unroll
        for (int i = 0; i < 4; i++) {
            s[i][0]*=scale; s[i][1]*=scale; s[i][2]*=scale; s[i][3]*=scale;
            float mm = fmaxf(fmaxf(s[i][0],s[i][1]), fmaxf(s[i][2],s[i][3]));
            mm = fmaxf(mm, __shfl_xor_sync(0xffffffffu, mm, 1));
            mm = fmaxf(mm, __shfl_xor_sync(0xffffffffu, mm, 2));
            mm = fmaxf(mm, __shfl_xor_sync(0xffffffffu, mm, 4));
            mm = fmaxf(mm, __shfl_xor_sync(0xffffffffu, mm, 8));
            float mn = fmaxf(mi[i], mm);
            float p0 = __expf(s[i][0]-mn), p1 = __expf(s[i][1]-mn);
            float p2 = __expf(s[i][2]-mn), p3 = __expf(s[i][3]-mn);
            float rsum = p0+p1+p2+p3;
            rsum += __shfl_xor_sync(0xffffffffu, rsum, 1);
            rsum += __shfl_xor_sync(0xffffffffu, rsum, 2);
            rsum += __shfl_xor_sync(0xffffffffu, rsum, 4);
            rsum += __shfl_xor_sync(0xffffffffu, rsum, 8);
            float alpha = __expf(mi[i]-mn);
            li[i] = li[i]*alpha + rsum;
            mi[i] = mn;
            #pragma unroll
            for (int jj = 0; jj < 8; jj++) acc[i][jj] *= alpha;
            float* pr = &Ps[(ty*4+i)*65 + tx*4];
            pr[0]=p0; pr[1]=p1; pr[2]=p2; pr[3]=p3;
        }
        __syncthreads();

        // O += P @ V
        #pragma unroll 2
        for (int n = 0; n < 64; n++) {
            float4 v0 = *(const float4*)&Vs[n*128 + tx*8];
            float4 v1 = *(const float4*)&Vs[n*128 + tx*8 + 4];
            #pragma unroll
            for (int i = 0; i < 4; i++) {
                float pp = Ps[(ty*4+i)*65 + n];
                acc[i][0] += pp*v0.x; acc[i][1] += pp*v0.y;
                acc[i][2] += pp*v0.z; acc[i][3] += pp*v0.w;
                acc[i][4] += pp*v1.x; acc[i][5] += pp*v1.y;
                acc[i][6] += pp*v1.z; acc[i][7] += pp*v1.w;
            }
        }
        __syncthreads();
    }

    // Epilogue: normalize and store
    #pragma unroll
    for (int i = 0; i < 4; i++) {
        float inv = 1.0f / li[i];
        float4 o0 = {acc[i][0]*inv, acc[i][1]*inv, acc[i][2]*inv, acc[i][3]*inv};
        float4 o1 = {acc[i][4]*inv, acc[i][5]*inv, acc[i][6]*inv, acc[i][7]*inv};
        float* op = &Op[(size_t)(m0 + ty*4 + i)*(NH*HD) + h*HD + tx*8];
        *(float4*)op       = o0;
        *(float4*)(op + 4) = o1;
    }
}

// ---------------------------------------------------------------------------
extern "C" void kernel_launch(void* const* d_in, const int* in_sizes, int n_in,
                              void* d_out, int out_size) {
    const float* x    = (const float*)d_in[0];
    const float* cosp = (const float*)d_in[1];
    const float* sinp = (const float*)d_in[2];
    const float* wq   = (const float*)d_in[3];
    const float* wk   = (const float*)d_in[4];
    const float* wv   = (const float*)d_in[5];
    const float* wo   = (const float*)d_in[6];
    float* out = (float*)d_out;

    float *Qb, *Kb, *Vb, *Ob;
    cudaGetSymbolAddress((void**)&Qb, g_Q);
    cudaGetSymbolAddress((void**)&Kb, g_K);
    cudaGetSymbolAddress((void**)&Vb, g_V);
    cudaGetSymbolAddress((void**)&Ob, g_O);

    cudaFuncSetAttribute(flash_kernel,
                         cudaFuncAttributeMaxDynamicSharedMemorySize, SMEM_FLASH);

    // Projections
    gemm_nt<<<dim3((NH*HD)/128,  MM/128), 256>>>(x, wq, Qb, MM, NH*HD,  HID);
    gemm_nt<<<dim3((NKV*HD)/128, MM/128), 256>>>(x, wk, Kb, MM, NKV*HD, HID);
    gemm_nt<<<dim3((NKV*HD)/128, MM/128), 256>>>(x, wv, Vb, MM, NKV*HD, HID);

    // RoPE
    rope_kernel<<<(MM*NH*64  + 255)/256, 256>>>(Qb, cosp, sinp, NH);
    rope_kernel<<<(MM*NKV*64 + 255)/256, 256>>>(Kb, cosp, sinp, NKV);

    // Attention
    flash_kernel<<<dim3(Ss/64, NH, Bb), 256, SMEM_FLASH>>>(Qb, Kb, Vb, Ob);

    // Output projection
    gemm_nt<<<dim3(HID/128, MM/128), 256>>>(Ob, wo, out, MM, HID, HID);
}

// round 2
// speedup vs baseline: 2.4234x; 2.4234x over previous
#include <cuda_runtime.h>
#include <math_constants.h>
#include <cstdint>

#define Bb   4
#define Ss   2048
#define HID  2048
#define NH   16
#define NKV  4
#define HD   128
#define MM   (Bb*Ss)   // 8192

// Scratch (device globals: allocation-free)
__device__ float g_Q[MM*NH*HD];
__device__ float g_K[MM*NKV*HD];
__device__ float g_V[MM*NKV*HD];
__device__ float g_O[MM*NH*HD];

__device__ __forceinline__ uint32_t f2tf(float x) {
    uint32_t r;
    asm("cvt.rna.tf32.f32 %0, %1;" : "=r"(r) : "f"(x));
    return r;
}

__device__ __forceinline__ void mma_tf32(float* c, const uint32_t* a, const uint32_t* b) {
    asm volatile(
        "mma.sync.aligned.m16n8k8.row.col.f32.tf32.tf32.f32 "
        "{%0,%1,%2,%3}, {%4,%5,%6,%7}, {%8,%9}, {%0,%1,%2,%3};"
        : "+f"(c[0]), "+f"(c[1]), "+f"(c[2]), "+f"(c[3])
        : "r"(a[0]), "r"(a[1]), "r"(a[2]), "r"(a[3]), "r"(b[0]), "r"(b[1]));
}

// ---------------------------------------------------------------------------
// TF32 GEMM: C[M,N] = A[M,K] @ W[N,K]^T   (row-major, K-contig)
// BM=BN=128, BK=16, 256 threads, 8 warps (2m x 4n), warp tile 64x32.
// ---------------------------------------------------------------------------
__global__ __launch_bounds__(256, 1) void gemm_tf32(const float* __restrict__ A,
                                                    const float* __restrict__ W,
                                                    float* __restrict__ C,
                                                    int M, int N, int K) {
    __shared__ uint32_t As[128*20];
    __shared__ uint32_t Ws[128*20];
    int t = threadIdx.x;
    int wid = t >> 5, lane = t & 31, g = lane >> 2, tg = lane & 3;
    int wm = (wid & 1) * 64, wn = (wid >> 1) * 32;
    int m0 = blockIdx.y * 128, n0 = blockIdx.x * 128;

    int lr = t >> 2, lc = (t & 3) * 4;
    const float* A0 = A + (size_t)(m0 + lr) * K + lc;
    const float* A1 = A + (size_t)(m0 + lr + 64) * K + lc;
    const float* W0 = W + (size_t)(n0 + lr) * K + lc;
    const float* W1 = W + (size_t)(n0 + lr + 64) * K + lc;

    float4 pa0 = *(const float4*)A0;
    float4 pa1 = *(const float4*)A1;
    float4 pw0 = *(const float4*)W0;
    float4 pw1 = *(const float4*)W1;

    float acc[4][4][4] = {};

    for (int k0 = 0; k0 < K; k0 += 16) {
        uint32_t* s;
        s = &As[lr*20 + lc];        s[0]=f2tf(pa0.x); s[1]=f2tf(pa0.y); s[2]=f2tf(pa0.z); s[3]=f2tf(pa0.w);
        s = &As[(lr+64)*20 + lc];   s[0]=f2tf(pa1.x); s[1]=f2tf(pa1.y); s[2]=f2tf(pa1.z); s[3]=f2tf(pa1.w);
        s = &Ws[lr*20 + lc];        s[0]=f2tf(pw0.x); s[1]=f2tf(pw0.y); s[2]=f2tf(pw0.z); s[3]=f2tf(pw0.w);
        s = &Ws[(lr+64)*20 + lc];   s[0]=f2tf(pw1.x); s[1]=f2tf(pw1.y); s[2]=f2tf(pw1.z); s[3]=f2tf(pw1.w);
        __syncthreads();

        if (k0 + 16 < K) {
            pa0 = *(const float4*)(A0 + k0 + 16);
            pa1 = *(const float4*)(A1 + k0 + 16);
            pw0 = *(const float4*)(W0 + k0 + 16);
            pw1 = *(const float4*)(W1 + k0 + 16);
        }

        #pragma unroll
        for (int ks = 0; ks < 16; ks += 8) {
            uint32_t af[4][4], bf[4][2];
            #pragma unroll
            for (int mt = 0; mt < 4; mt++) {
                int rb = wm + mt*16;
                af[mt][0] = As[(rb + g)*20 + ks + tg];
                af[mt][1] = As[(rb + g + 8)*20 + ks + tg];
                af[mt][2] = As[(rb + g)*20 + ks + tg + 4];
                af[mt][3] = As[(rb + g + 8)*20 + ks + tg + 4];
            }
            #pragma unroll
            for (int nt = 0; nt < 4; nt++) {
                bf[nt][0] = Ws[(wn + nt*8 + g)*20 + ks + tg];
                bf[nt][1] = Ws[(wn + nt*8 + g)*20 + ks + tg + 4];
            }
            #pragma unroll
            for (int mt = 0; mt < 4; mt++)
                #pragma unroll
                for (int nt = 0; nt < 4; nt++)
                    mma_tf32(acc[mt][nt], af[mt], bf[nt]);
        }
        __syncthreads();
    }

    #pragma unroll
    for (int mt = 0; mt < 4; mt++) {
        #pragma unroll
        for (int nt = 0; nt < 4; nt++) {
            int row = m0 + wm + mt*16 + g;
            int col = n0 + wn + nt*8 + 2*tg;
            float2 v0 = {acc[mt][nt][0], acc[mt][nt][1]};
            float2 v1 = {acc[mt][nt][2], acc[mt][nt][3]};
            *(float2*)&C[(size_t)row * N + col] = v0;
            *(float2*)&C[(size_t)(row + 8) * N + col] = v1;
        }
    }
}

// ---------------------------------------------------------------------------
// RoPE (in place). t: [MM][nh*HD]. cos/sin: [Ss][HD], duplicated halves.
// ---------------------------------------------------------------------------
__global__ void rope_kernel(float* __restrict__ t,
                            const float* __restrict__ cosp,
                            const float* __restrict__ sinp, int nh) {
    int idx = blockIdx.x * blockDim.x + threadIdx.x;
    int total = MM * nh * 64;
    if (idx >= total) return;
    int d = idx & 63;
    int h = (idx >> 6) % nh;
    int m = idx / (64 * nh);
    int s = m & (Ss - 1);
    float c  = cosp[s*HD + d];
    float sn = sinp[s*HD + d];
    float* p = t + (size_t)m * nh * HD + h * HD;
    float x1 = p[d], x2 = p[d + 64];
    p[d]      = x1*c - x2*sn;
    p[d + 64] = x2*c + x1*sn;
}

// ---------------------------------------------------------------------------
// Flash attention, TF32 mma. Q tile 128 rows, KV tile 64, 8 warps x 16 rows.
// Grid: (Ss/128, NH, Bb), 256 threads.
// ---------------------------------------------------------------------------
#define QS_W 132
#define VT_W 68
#define FLASH_WORDS (128*QS_W + 64*QS_W + 128*VT_W + 128*VT_W)
#define FLASH_SMEM  (FLASH_WORDS * 4)

__global__ __launch_bounds__(256, 1) void flash_tf32(const float* __restrict__ Qp,
                                                     const float* __restrict__ Kp,
                                                     const float* __restrict__ Vp,
                                                     float* __restrict__ Op) {
    extern __shared__ uint32_t sm[];
    uint32_t* Qs = sm;                       // [128][132]
    uint32_t* Ks = Qs + 128*QS_W;            // [64][132]
    uint32_t* Vt = Ks + 64*QS_W;             // [128][68]  (V transposed: [d][token])
    uint32_t* Ps = Vt + 128*VT_W;            // [128][68]

    int t = threadIdx.x;
    int wid = t >> 5, lane = t & 31, g = lane >> 2, tg = lane & 3;
    int h = blockIdx.y, b = blockIdx.z;
    int kv = h >> 2;
    size_t mbase = (size_t)b * Ss + blockIdx.x * 128;
    int wm = wid * 16;
    const float scale = 0.08838834764831845f;  // 1/sqrt(128)

    // Load Q tile (scale folded in)
    #pragma unroll
    for (int i = 0; i < 16; i++) {
        int idx = i*256 + t;
        int row = idx >> 5, c4 = (idx & 31) * 4;
        float4 v = *(const float4*)&Qp[(mbase + row)*(NH*HD) + h*HD + c4];
        uint32_t* q = &Qs[row*QS_W + c4];
        q[0]=f2tf(v.x*scale); q[1]=f2tf(v.y*scale); q[2]=f2tf(v.z*scale); q[3]=f2tf(v.w*scale);
    }

    float oacc[16][4] = {};
    float mi0 = -CUDART_INF_F, mi1 = -CUDART_INF_F;
    float li0 = 0.f, li1 = 0.f;

    for (int n0 = 0; n0 < Ss; n0 += 64) {
        // Load K (row-major) and V (transposed) tiles
        #pragma unroll
        for (int i = 0; i < 8; i++) {
            int idx = i*256 + t;
            int row = idx >> 5, c4 = (idx & 31) * 4;
            size_t ga = ((size_t)b*Ss + n0 + row)*(NKV*HD) + kv*HD + c4;
            float4 kk = *(const float4*)&Kp[ga];
            uint32_t* kd = &Ks[row*QS_W + c4];
            kd[0]=f2tf(kk.x); kd[1]=f2tf(kk.y); kd[2]=f2tf(kk.z); kd[3]=f2tf(kk.w);
            float4 vv = *(const float4*)&Vp[ga];
            Vt[(c4+0)*VT_W + row] = f2tf(vv.x);
            Vt[(c4+1)*VT_W + row] = f2tf(vv.y);
            Vt[(c4+2)*VT_W + row] = f2tf(vv.z);
            Vt[(c4+3)*VT_W + row] = f2tf(vv.w);
        }
        __syncthreads();

        // S = Q K^T (warp: 16 rows x 64 cols)
        float sacc[8][4] = {};
        #pragma unroll
        for (int ks = 0; ks < 128; ks += 8) {
            uint32_t af[4];
            af[0] = Qs[(wm + g)*QS_W + ks + tg];
            af[1] = Qs[(wm + g + 8)*QS_W + ks + tg];
            af[2] = Qs[(wm + g)*QS_W + ks + tg + 4];
            af[3] = Qs[(wm + g + 8)*QS_W + ks + tg + 4];
            #pragma unroll
            for (int nt = 0; nt < 8; nt++) {
                uint32_t bf[2];
                bf[0] = Ks[(nt*8 + g)*QS_W + ks + tg];
                bf[1] = Ks[(nt*8 + g)*QS_W + ks + tg + 4];
                mma_tf32(sacc[nt], af, bf);
            }
        }

        // Online softmax (rows g and g+8 of the warp tile)
        float m0l = -CUDART_INF_F, m1l = -CUDART_INF_F;
        #pragma unroll
        for (int nt = 0; nt < 8; nt++) {
            m0l = fmaxf(m0l, fmaxf(sacc[nt][0], sacc[nt][1]));
            m1l = fmaxf(m1l, fmaxf(sacc[nt][2], sacc[nt][3]));
        }
        m0l = fmaxf(m0l, __shfl_xor_sync(0xffffffffu, m0l, 1));
        m0l = fmaxf(m0l, __shfl_xor_sync(0xffffffffu, m0l, 2));
        m1l = fmaxf(m1l, __shfl_xor_sync(0xffffffffu, m1l, 1));
        m1l = fmaxf(m1l, __shfl_xor_sync(0xffffffffu, m1l, 2));

        float mn0 = fmaxf(mi0, m0l), mn1 = fmaxf(mi1, m1l);
        float al0 = __expf(mi0 - mn0), al1 = __expf(mi1 - mn1);
        mi0 = mn0; mi1 = mn1;

        float s0 = 0.f, s1 = 0.f;
        #pragma unroll
        for (int nt = 0; nt < 8; nt++) {
            float p0 = __expf(sacc[nt][0] - mn0);
            float p1 = __expf(sacc[nt][1] - mn0);
            float p2 = __expf(sacc[nt][2] - mn1);
            float p3 = __expf(sacc[nt][3] - mn1);
            s0 += p0 + p1;  s1 += p2 + p3;
            uint32_t* pr = &Ps[(wm + g)*VT_W + nt*8 + 2*tg];
            pr[0] = f2tf(p0); pr[1] = f2tf(p1);
            pr = &Ps[(wm + g + 8)*VT_W + nt*8 + 2*tg];
            pr[0] = f2tf(p2); pr[1] = f2tf(p3);
        }
        s0 += __shfl_xor_sync(0xffffffffu, s0, 1);
        s0 += __shfl_xor_sync(0xffffffffu, s0, 2);
        s1 += __shfl_xor_sync(0xffffffffu, s1, 1);
        s1 += __shfl_xor_sync(0xffffffffu, s1, 2);
        li0 = li0*al0 + s0;
        li1 = li1*al1 + s1;

        #pragma unroll
        for (int nt = 0; nt < 16; nt++) {
            oacc[nt][0] *= al0; oacc[nt][1] *= al0;
            oacc[nt][2] *= al1; oacc[nt][3] *= al1;
        }
        __syncwarp();

        // O += P @ V   (A = Ps warp rows, B = Vt)
        #pragma unroll
        for (int ks = 0; ks < 64; ks += 8) {
            uint32_t af[4];
            af[0] = Ps[(wm + g)*VT_W + ks + tg];
            af[1] = Ps[(wm + g + 8)*VT_W + ks + tg];
            af[2] = Ps[(wm + g)*VT_W + ks + tg + 4];
            af[3] = Ps[(wm + g + 8)*VT_W + ks + tg + 4];
            #pragma unroll
            for (int nt = 0; nt < 16; nt++) {
                uint32_t bf[2];
                bf[0] = Vt[(nt*8 + g)*VT_W + ks + tg];
                bf[1] = Vt[(nt*8 + g)*VT_W + ks + tg + 4];
                mma_tf32(oacc[nt], af, bf);
            }
        }
        __syncthreads();
    }

    // Epilogue
    float i0 = 1.f / li0, i1 = 1.f / li1;
    #pragma unroll
    for (int nt = 0; nt < 16; nt++) {
        int col = h*HD + nt*8 + 2*tg;
        size_t row = mbase + wm + g;
        float2 v0 = {oacc[nt][0]*i0, oacc[nt][1]*i0};
        float2 v1 = {oacc[nt][2]*i1, oacc[nt][3]*i1};
        *(float2*)&Op[row*(NH*HD) + col] = v0;
        *(float2*)&Op[(row + 8)*(NH*HD) + col] = v1;
    }
}

// ---------------------------------------------------------------------------
extern "C" void kernel_launch(void* const* d_in, const int* in_sizes, int n_in,
                              void* d_out, int out_size) {
    const float* x    = (const float*)d_in[0];
    const float* cosp = (const float*)d_in[1];
    const float* sinp = (const float*)d_in[2];
    const float* wq   = (const float*)d_in[3];
    const float* wk   = (const float*)d_in[4];
    const float* wv   = (const float*)d_in[5];
    const float* wo   = (const float*)d_in[6];
    float* out = (float*)d_out;

    float *Qb, *Kb, *Vb, *Ob;
    cudaGetSymbolAddress((void**)&Qb, g_Q);
    cudaGetSymbolAddress((void**)&Kb, g_K);
    cudaGetSymbolAddress((void**)&Vb, g_V);
    cudaGetSymbolAddress((void**)&Ob, g_O);

    cudaFuncSetAttribute(flash_tf32,
                         cudaFuncAttributeMaxDynamicSharedMemorySize, FLASH_SMEM);

    // Projections
    gemm_tf32<<<dim3((NH*HD)/128,  MM/128), 256>>>(x, wq, Qb, MM, NH*HD,  HID);
    gemm_tf32<<<dim3((NKV*HD)/128, MM/128), 256>>>(x, wk, Kb, MM, NKV*HD, HID);
    gemm_tf32<<<dim3((NKV*HD)/128, MM/128), 256>>>(x, wv, Vb, MM, NKV*HD, HID);

    // RoPE
    rope_kernel<<<(MM*NH*64  + 255)/256, 256>>>(Qb, cosp, sinp, NH);
    rope_kernel<<<(MM*NKV*64 + 255)/256, 256>>>(Kb, cosp, sinp, NKV);

    // Attention
    flash_tf32<<<dim3(Ss/128, NH, Bb), 256, FLASH_SMEM>>>(Qb, Kb, Vb, Ob);

    // Output projection
    gemm_tf32<<<dim3(HID/128, MM/128), 256>>>(Ob, wo, out, MM, HID, HID);
}

// round 4
// speedup vs baseline: 4.7622x; 1.9651x over previous
#include <cuda_runtime.h>
#include <cuda_fp16.h>
#include <math_constants.h>
#include <cstdint>

#define Bb   4
#define Ss   2048
#define HID  2048
#define NH   16
#define NKV  4
#define HD   128
#define MM   (Bb*Ss)   // 8192

// Scratch (device globals, half precision)
__device__ __half g_Q[MM*NH*HD];
__device__ __half g_K[MM*NKV*HD];
__device__ __half g_V[MM*NKV*HD];
__device__ __half g_O[MM*NH*HD];

__device__ __forceinline__ uint32_t h2pack(float lo, float hi) {
    uint32_t r;
    asm("cvt.rn.f16x2.f32 %0, %1, %2;" : "=r"(r) : "f"(hi), "f"(lo));
    return r;
}

__device__ __forceinline__ uint32_t smem_u32(const void* p) {
    uint32_t a;
    asm("{ .reg .u64 t; cvta.to.shared.u64 t, %1; cvt.u32.u64 %0, t; }" : "=r"(a) : "l"(p));
    return a;
}

__device__ __forceinline__ void sts64(uint32_t addr, uint32_t a, uint32_t b) {
    asm volatile("st.shared.v2.b32 [%0], {%1,%2};" :: "r"(addr), "r"(a), "r"(b));
}

__device__ __forceinline__ void ldmA4(uint32_t* r, uint32_t addr) {
    asm volatile("ldmatrix.sync.aligned.m8n8.x4.shared.b16 {%0,%1,%2,%3}, [%4];"
        : "=r"(r[0]), "=r"(r[1]), "=r"(r[2]), "=r"(r[3]) : "r"(addr));
}
__device__ __forceinline__ void ldmB2(uint32_t* r, uint32_t addr) {
    asm volatile("ldmatrix.sync.aligned.m8n8.x2.shared.b16 {%0,%1}, [%2];"
        : "=r"(r[0]), "=r"(r[1]) : "r"(addr));
}
__device__ __forceinline__ void ldmB2T(uint32_t* r, uint32_t addr) {
    asm volatile("ldmatrix.sync.aligned.m8n8.x2.trans.shared.b16 {%0,%1}, [%2];"
        : "=r"(r[0]), "=r"(r[1]) : "r"(addr));
}

__device__ __forceinline__ void mma_h(float* c, const uint32_t* a, const uint32_t* b) {
    asm volatile(
        "mma.sync.aligned.m16n8k16.row.col.f32.f16.f16.f32 "
        "{%0,%1,%2,%3}, {%4,%5,%6,%7}, {%8,%9}, {%0,%1,%2,%3};"
        : "+f"(c[0]), "+f"(c[1]), "+f"(c[2]), "+f"(c[3])
        : "r"(a[0]), "r"(a[1]), "r"(a[2]), "r"(a[3]), "r"(b[0]), "r"(b[1]));
}

// ---------------------------------------------------------------------------
// FP16 GEMM: C[M,N] = A[M,K] @ W[N,K]^T.  A fp32 or fp16; W fp32; C fp32/fp16.
// BM=BN=128, BK=32, 256 threads (8 warps 2x4), 2-stage smem + reg prefetch.
// smem rows padded to 80B (40 halfs) -> conflict-free ldmatrix.
// ---------------------------------------------------------------------------
#define GSTG 20480            // bytes per stage (A 10240 + B 10240)
#define GEMM_SMEM (2*GSTG)

template<bool AHALF, bool OHALF>
__global__ __launch_bounds__(256) void gemm_h(const void* __restrict__ Av,
                                              const float* __restrict__ W,
                                              void* __restrict__ Cv,
                                              int M, int N, int K) {
    extern __shared__ char smc[];
    uint32_t sb = smem_u32(smc);
    int t = threadIdx.x, wid = t >> 5, lane = t & 31;
    int g = lane >> 2, tg = lane & 3;
    int wm = (wid & 1) * 64, wn = (wid >> 1) * 32;
    int m0 = blockIdx.y * 128, n0 = blockIdx.x * 128;

    const float* Af = (const float*)Av;
    const __half* Ah = (const __half*)Av;

    int row_ld = t >> 3, seg = t & 7;       // per-j: row = row_ld + j*32
    float4 raf[4]; uint2 rah[4]; float4 rbf[4];

    // ---- load stage 0 into regs
    #pragma unroll
    for (int j = 0; j < 4; j++) {
        int row = row_ld + j*32;
        if (AHALF) rah[j] = *(const uint2*)(Ah + (size_t)(m0 + row)*K + seg*4);
        else       raf[j] = *(const float4*)(Af + (size_t)(m0 + row)*K + seg*4);
        rbf[j] = *(const float4*)(W + (size_t)(n0 + row)*K + seg*4);
    }

    float acc[4][4][4] = {};
    int NIT = K >> 5;

    // ---- STS stage 0
    {
        uint32_t ab = sb, bbs = sb + 10240;
        #pragma unroll
        for (int j = 0; j < 4; j++) {
            int row = row_ld + j*32;
            uint32_t off = row*80 + seg*8;
            if (AHALF) sts64(ab + off, rah[j].x, rah[j].y);
            else       sts64(ab + off, h2pack(raf[j].x, raf[j].y), h2pack(raf[j].z, raf[j].w));
            sts64(bbs + off, h2pack(rbf[j].x, rbf[j].y), h2pack(rbf[j].z, rbf[j].w));
        }
    }
    __syncthreads();

    for (int i = 0; i < NIT; i++) {
        // prefetch next stage to regs
        if (i + 1 < NIT) {
            int k0 = (i + 1) << 5;
            #pragma unroll
            for (int j = 0; j < 4; j++) {
                int row = row_ld + j*32;
                if (AHALF) rah[j] = *(const uint2*)(Ah + (size_t)(m0 + row)*K + k0 + seg*4);
                else       raf[j] = *(const float4*)(Af + (size_t)(m0 + row)*K + k0 + seg*4);
                rbf[j] = *(const float4*)(W + (size_t)(n0 + row)*K + k0 + seg*4);
            }
        }

        // compute current stage
        uint32_t ab = sb + (i & 1)*GSTG, bbs = ab + 10240;
        #pragma unroll
        for (int ks = 0; ks < 64; ks += 32) {
            uint32_t a[4][4];
            #pragma unroll
            for (int mt = 0; mt < 4; mt++)
                ldmA4(a[mt], ab + (wm + mt*16 + (lane & 15))*80 + ks + (lane >> 4)*16);
            #pragma unroll
            for (int nt = 0; nt < 4; nt++) {
                uint32_t bf[2];
                ldmB2(bf, bbs + (wn + nt*8 + (lane & 7))*80 + ks + ((lane >> 3) & 1)*16);
                #pragma unroll
                for (int mt = 0; mt < 4; mt++)
                    mma_h(acc[mt][nt], a[mt], bf);
            }
        }

        // STS next stage
        if (i + 1 < NIT) {
            uint32_t ab2 = sb + ((i + 1) & 1)*GSTG, bb2 = ab2 + 10240;
            #pragma unroll
            for (int j = 0; j < 4; j++) {
                int row = row_ld + j*32;
                uint32_t off = row*80 + seg*8;
                if (AHALF) sts64(ab2 + off, rah[j].x, rah[j].y);
                else       sts64(ab2 + off, h2pack(raf[j].x, raf[j].y), h2pack(raf[j].z, raf[j].w));
                sts64(bb2 + off, h2pack(rbf[j].x, rbf[j].y), h2pack(rbf[j].z, rbf[j].w));
            }
        }
        __syncthreads();
    }

    // epilogue
    #pragma unroll
    for (int mt = 0; mt < 4; mt++) {
        #pragma unroll
        for (int nt = 0; nt < 4; nt++) {
            int row = m0 + wm + mt*16 + g;
            int col = n0 + wn + nt*8 + 2*tg;
            if (OHALF) {
                __half* Ch = (__half*)Cv;
                *(uint32_t*)(Ch + (size_t)row*N + col)       = h2pack(acc[mt][nt][0], acc[mt][nt][1]);
                *(uint32_t*)(Ch + (size_t)(row + 8)*N + col) = h2pack(acc[mt][nt][2], acc[mt][nt][3]);
            } else {
                float* Cf = (float*)Cv;
                float2 v0 = {acc[mt][nt][0], acc[mt][nt][1]};
                float2 v1 = {acc[mt][nt][2], acc[mt][nt][3]};
                *(float2*)(Cf + (size_t)row*N + col)       = v0;
                *(float2*)(Cf + (size_t)(row + 8)*N + col) = v1;
            }
        }
    }
}

// ---------------------------------------------------------------------------
// Flash attention fp16, RoPE fused into Q/K loads. Q tile 128, KV tile 64.
// 8 warps x 16 q-rows. Grid (Ss/128, NH, Bb), 256 threads.
// smem halfs: Qs[128][136], Ks[64][136], Vs[64][136], Ps[128][72]
// ---------------------------------------------------------------------------
#define QPITCH 272   // bytes per Q/K/V row (136 halfs)
#define PPITCH 144   // bytes per P row (72 halfs)
#define OFF_Q  0
#define OFF_K  (128*QPITCH)
#define OFF_V  (OFF_K + 64*QPITCH)
#define OFF_P  (OFF_V + 64*QPITCH)
#define FLASH_SMEM (OFF_P + 128*PPITCH)   // 88064

__global__ __launch_bounds__(256) void flash_h(const __half* __restrict__ Qp,
                                               const __half* __restrict__ Kp,
                                               const __half* __restrict__ Vp,
                                               __half* __restrict__ Op,
                                               const float* __restrict__ cosp,
                                               const float* __restrict__ sinp) {
    extern __shared__ char smc[];
    uint32_t sb = smem_u32(smc);
    uint32_t Qs = sb + OFF_Q, Ks = sb + OFF_K, Vs = sb + OFF_V, Ps = sb + OFF_P;

    int t = threadIdx.x;
    int wid = t >> 5, lane = t & 31, g = lane >> 2, tg = lane & 3;
    int h = blockIdx.y, b = blockIdx.z;
    int kv = h >> 2;
    size_t mbase = (size_t)b * Ss + blockIdx.x * 128;
    int wm = wid * 16;
    const float scale = 0.08838834764831845f;

    // ---- Q tile load + RoPE + scale (half in, half out)
    #pragma unroll
    for (int i = 0; i < 8; i++) {
        int pid = i*256 + t;
        int row = pid >> 4, qd = (pid & 15) * 4;
        const __half* qp = Qp + (mbase + row)*(NH*HD) + h*HD;
        uint2 u1 = *(const uint2*)(qp + qd);
        uint2 u2 = *(const uint2*)(qp + qd + 64);
        float2 x1a = __half22float2(*(__half2*)&u1.x), x1b = __half22float2(*(__half2*)&u1.y);
        float2 x2a = __half22float2(*(__half2*)&u2.x), x2b = __half22float2(*(__half2*)&u2.y);
        int s = blockIdx.x*128 + row;
        float4 cc = *(const float4*)(cosp + s*HD + qd);
        float4 sn = *(const float4*)(sinp + s*HD + qd);
        float e1x = (x1a.x*cc.x - x2a.x*sn.x)*scale, e1y = (x1a.y*cc.y - x2a.y*sn.y)*scale;
        float e1z = (x1b.x*cc.z - x2b.x*sn.z)*scale, e1w = (x1b.y*cc.w - x2b.y*sn.w)*scale;
        float e2x = (x2a.x*cc.x + x1a.x*sn.x)*scale, e2y = (x2a.y*cc.y + x1a.y*sn.y)*scale;
        float e2z = (x2b.x*cc.z + x1b.x*sn.z)*scale, e2w = (x2b.y*cc.w + x1b.y*sn.w)*scale;
        sts64(Qs + row*QPITCH + qd*2,        h2pack(e1x, e1y), h2pack(e1z, e1w));
        sts64(Qs + row*QPITCH + (qd+64)*2,   h2pack(e2x, e2y), h2pack(e2z, e2w));
    }

    float oacc[16][4] = {};
    float mi0 = -CUDART_INF_F, mi1 = -CUDART_INF_F;
    float li0 = 0.f, li1 = 0.f;

    for (int n0 = 0; n0 < Ss; n0 += 64) {
        // ---- K tile + RoPE
        #pragma unroll
        for (int i = 0; i < 4; i++) {
            int pid = i*256 + t;
            int row = pid >> 4, kd = (pid & 15) * 4;
            const __half* kp = Kp + ((size_t)b*Ss + n0 + row)*(NKV*HD) + kv*HD;
            uint2 u1 = *(const uint2*)(kp + kd);
            uint2 u2 = *(const uint2*)(kp + kd + 64);
            float2 x1a = __half22float2(*(__half2*)&u1.x), x1b = __half22float2(*(__half2*)&u1.y);
            float2 x2a = __half22float2(*(__half2*)&u2.x), x2b = __half22float2(*(__half2*)&u2.y);
            int s = n0 + row;
            float4 cc = *(const float4*)(cosp + s*HD + kd);
            float4 sn = *(const float4*)(sinp + s*HD + kd);
            float e1x = x1a.x*cc.x - x2a.x*sn.x, e1y = x1a.y*cc.y - x2a.y*sn.y;
            float e1z = x1b.x*cc.z - x2b.x*sn.z, e1w = x1b.y*cc.w - x2b.y*sn.w;
            float e2x = x2a.x*cc.x + x1a.x*sn.x, e2y = x2a.y*cc.y + x1a.y*sn.y;
            float e2z = x2b.x*cc.z + x1b.x*sn.z, e2w = x2b.y*cc.w + x1b.y*sn.w;
            sts64(Ks + row*QPITCH + kd*2,      h2pack(e1x, e1y), h2pack(e1z, e1w));
            sts64(Ks + row*QPITCH + (kd+64)*2, h2pack(e2x, e2y), h2pack(e2z, e2w));
        }
        // ---- V tile (straight half copy)
        #pragma unroll
        for (int i = 0; i < 8; i++) {
            int pid = i*256 + t;
            int row = pid >> 5, vd = (pid & 31) * 4;
            uint2 u = *(const uint2*)(Vp + ((size_t)b*Ss + n0 + row)*(NKV*HD) + kv*HD + vd);
            sts64(Vs + row*QPITCH + vd*2, u.x, u.y);
        }
        __syncthreads();

        // ---- S = Q K^T  (warp: 16 rows x 64 cols)
        float sacc[8][4] = {};
        #pragma unroll
        for (int ks = 0; ks < 8; ks++) {
            uint32_t a[4];
            ldmA4(a, Qs + (wm + (lane & 15))*QPITCH + ks*32 + (lane >> 4)*16);
            #pragma unroll
            for (int nt = 0; nt < 8; nt++) {
                uint32_t bf[2];
                ldmB2(bf, Ks + (nt*8 + (lane & 7))*QPITCH + ks*32 + ((lane >> 3) & 1)*16);
                mma_h(sacc[nt], a, bf);
            }
        }

        // ---- online softmax
        float m0l = -CUDART_INF_F, m1l = -CUDART_INF_F;
        #pragma unroll
        for (int nt = 0; nt < 8; nt++) {
            m0l = fmaxf(m0l, fmaxf(sacc[nt][0], sacc[nt][1]));
            m1l = fmaxf(m1l, fmaxf(sacc[nt][2], sacc[nt][3]));
        }
        m0l = fmaxf(m0l, __shfl_xor_sync(0xffffffffu, m0l, 1));
        m0l = fmaxf(m0l, __shfl_xor_sync(0xffffffffu, m0l, 2));
        m1l = fmaxf(m1l, __shfl_xor_sync(0xffffffffu, m1l, 1));
        m1l = fmaxf(m1l, __shfl_xor_sync(0xffffffffu, m1l, 2));

        float mn0 = fmaxf(mi0, m0l), mn1 = fmaxf(mi1, m1l);
        float al0 = __expf(mi0 - mn0), al1 = __expf(mi1 - mn1);
        mi0 = mn0; mi1 = mn1;

        float s0 = 0.f, s1 = 0.f;
        #pragma unroll
        for (int nt = 0; nt < 8; nt++) {
            float p0 = __expf(sacc[nt][0] - mn0);
            float p1 = __expf(sacc[nt][1] - mn0);
            float p2 = __expf(sacc[nt][2] - mn1);
            float p3 = __expf(sacc[nt][3] - mn1);
            s0 += p0 + p1;  s1 += p2 + p3;
            *(uint32_t*)(smc + (Ps - sb) + (wm + g)*PPITCH     + (nt*8 + 2*tg)*2) = h2pack(p0, p1);
            *(uint32_t*)(smc + (Ps - sb) + (wm + g + 8)*PPITCH + (nt*8 + 2*tg)*2) = h2pack(p2, p3);
        }
        s0 += __shfl_xor_sync(0xffffffffu, s0, 1);
        s0 += __shfl_xor_sync(0xffffffffu, s0, 2);
        s1 += __shfl_xor_sync(0xffffffffu, s1, 1);
        s1 += __shfl_xor_sync(0xffffffffu, s1, 2);
        li0 = li0*al0 + s0;
        li1 = li1*al1 + s1;

        #pragma unroll
        for (int nt = 0; nt < 16; nt++) {
            oacc[nt][0] *= al0; oacc[nt][1] *= al0;
            oacc[nt][2] *= al1; oacc[nt][3] *= al1;
        }
        __syncwarp();

        // ---- O += P @ V
        #pragma unroll
        for (int kst = 0; kst < 4; kst++) {
            uint32_t a[4];
            ldmA4(a, Ps + (wm + (lane & 15))*PPITCH + kst*32 + (lane >> 4)*16);
            #pragma unroll
            for (int nt = 0; nt < 16; nt++) {
                uint32_t bf[2];
                ldmB2T(bf, Vs + (kst*16 + (lane & 15))*QPITCH + nt*16);
                mma_h(oacc[nt], a, bf);
            }
        }
        __syncthreads();
    }

    float i0 = 1.f / li0, i1 = 1.f / li1;
    #pragma unroll
    for (int nt = 0; nt < 16; nt++) {
        int col = h*HD + nt*8 + 2*tg;
        size_t row = mbase + wm + g;
        *(uint32_t*)(Op + row*(NH*HD) + col)       = h2pack(oacc[nt][0]*i0, oacc[nt][1]*i0);
        *(uint32_t*)(Op + (row + 8)*(NH*HD) + col) = h2pack(oacc[nt][2]*i1, oacc[nt][3]*i1);
    }
}

// ---------------------------------------------------------------------------
extern "C" void kernel_launch(void* const* d_in, const int* in_sizes, int n_in,
                              void* d_out, int out_size) {
    const float* x    = (const float*)d_in[0];
    const float* cosp = (const float*)d_in[1];
    const float* sinp = (const float*)d_in[2];
    const float* wq   = (const float*)d_in[3];
    const float* wk   = (const float*)d_in[4];
    const float* wv   = (const float*)d_in[5];
    const float* wo   = (const float*)d_in[6];
    float* out = (float*)d_out;

    __half *Qb, *Kb, *Vb, *Ob;
    cudaGetSymbolAddress((void**)&Qb, g_Q);
    cudaGetSymbolAddress((void**)&Kb, g_K);
    cudaGetSymbolAddress((void**)&Vb, g_V);
    cudaGetSymbolAddress((void**)&Ob, g_O);

    cudaFuncSetAttribute(flash_h,
                         cudaFuncAttributeMaxDynamicSharedMemorySize, FLASH_SMEM);

    // Projections (fp32 in -> half out)
    gemm_h<false, true><<<dim3((NH*HD)/128,  MM/128), 256, GEMM_SMEM>>>(x, wq, Qb, MM, NH*HD,  HID);
    gemm_h<false, true><<<dim3((NKV*HD)/128, MM/128), 256, GEMM_SMEM>>>(x, wk, Kb, MM, NKV*HD, HID);
    gemm_h<false, true><<<dim3((NKV*HD)/128, MM/128), 256, GEMM_SMEM>>>(x, wv, Vb, MM, NKV*HD, HID);

    // Attention (RoPE fused)
    flash_h<<<dim3(Ss/128, NH, Bb), 256, FLASH_SMEM>>>(Qb, Kb, Vb, Ob, cosp, sinp);

    // Output projection (half A -> fp32 out)
    gemm_h<true, false><<<dim3(HID/128, MM/128), 256, GEMM_SMEM>>>(Ob, wo, out, MM, HID, HID);
}